// round 12
// baseline (speedup 1.0000x reference)
#include <cuda_runtime.h>
#include <math.h>

#define N_IN  8000
#define NS    4000
#define D     64
#define H     128
#define EK    15
#define KNN   16
#define NPAIR 120
#define MAXD  256
#define GRID  16
#define NCELL (GRID * GRID * GRID)
#define RCH   8
#define RCHN  (N_IN / RCH)   // 1000

// ---------------- scratch (no allocations allowed) ----------------
__device__ float g_prob[N_IN];
__device__ int   g_rank[N_IN];
__device__ int   g_sel[NS];
__device__ int   g_cnt[NS];
__device__ float g_sx[NS * D];
__device__ float g_sp[NS * 3];
__device__ float4 g_sp4[NS];
__device__ int   g_nbr[NS * EK];
__device__ int   g_deg[NS];
__device__ int   g_scol[NS * MAXD];    // unsorted buckets, then sorted CSR (in place)
__device__ float g_sval[NS * MAXD];
__device__ float g_norm[NS];
__device__ int   g_knn[NS * KNN];
__device__ float g_p[NS * H];
// spatial grid
__device__ int   g_ccnt[NCELL];
__device__ int   g_cstart[NCELL];
__device__ int   g_pcell[NS];
__device__ int   g_pslot[NS];
__device__ int   g_cpts[NS];

__device__ __forceinline__ float sigmoid_fast(float v) { return 1.0f / (1.0f + expf(-v)); }
// near-correctly-rounded fp32 sigmoid — matches libm expf bits
__device__ __forceinline__ float sigmoid_exact(float v) {
    float e = (float)exp(-(double)v);
    return __fdiv_rn(1.0f, __fadd_rn(1.0f, e));
}
__device__ __forceinline__ unsigned int f32_sortable(float f) {
    unsigned int b = __float_as_uint(f);
    return (b & 0x80000000u) ? ~b : (b | 0x80000000u);
}
// sorted-CSR point lookup (rows ascending in j)
__device__ __forceinline__ float adj_lookup(int r, int j) {
    const int* c = g_scol + r * MAXD;
    int n = g_deg[r];
    int lo = 0, hi = n;
    while (lo < hi) { int mid = (lo + hi) >> 1; if (c[mid] < j) lo = mid + 1; else hi = mid; }
    return (lo < n && c[lo] == j) ? g_sval[r * MAXD + lo] : 0.0f;
}

// ---------------- 1. probs = sigmoid(relu(x@W1 + b1) @ w2), Eigen bit-model ----------------
// Vectorized loads; scalar fma chains in identical ascending order (bit-preserving).
__global__ void k_logits(const float* __restrict__ x, const float* __restrict__ W1,
                         const float* __restrict__ b1, const float* __restrict__ w2) {
    __shared__ float sW[D * H];
    __shared__ float sw2[H];
    __shared__ float sb1[H];
    __shared__ float sh[8][H];
    int tid = threadIdx.x;
    int gt = blockIdx.x * blockDim.x + tid;
    if (gt < N_IN) g_rank[gt] = 0;
    if (gt < NS)   g_cnt[gt] = 0;
    if (gt < NCELL) g_ccnt[gt] = 0;
    for (int t = tid; t < D * H; t += blockDim.x) sW[t] = W1[t];
    if (tid < H) { sw2[tid] = w2[tid]; sb1[tid] = b1[tid]; }
    __syncthreads();
    int warp = gt >> 5;
    int wloc = (tid >> 5);
    int lane = tid & 31;
    if (warp >= N_IN) return;
    const float4* xr = (const float4*)(x + warp * D);   // row is 256B aligned
    float acc[4] = {0.f, 0.f, 0.f, 0.f};
#pragma unroll 4
    for (int d4 = 0; d4 < D / 4; d4++) {
        float4 xv = xr[d4];
        int d = d4 * 4;
#pragma unroll
        for (int q = 0; q < 4; q++) acc[q] = fmaf(xv.x, sW[(d + 0) * H + lane + q * 32], acc[q]);
#pragma unroll
        for (int q = 0; q < 4; q++) acc[q] = fmaf(xv.y, sW[(d + 1) * H + lane + q * 32], acc[q]);
#pragma unroll
        for (int q = 0; q < 4; q++) acc[q] = fmaf(xv.z, sW[(d + 2) * H + lane + q * 32], acc[q]);
#pragma unroll
        for (int q = 0; q < 4; q++) acc[q] = fmaf(xv.w, sW[(d + 3) * H + lane + q * 32], acc[q]);
    }
#pragma unroll
    for (int q = 0; q < 4; q++) {
        int j = lane + q * 32;
        sh[wloc][j] = fmaxf(__fadd_rn(acc[q], sb1[j]), 0.0f);
    }
    __syncwarp();
    if (lane == 0) {
        const float4* shv = (const float4*)sh[wloc];
        const float4* swv = (const float4*)sw2;
        float logit = 0.0f;
#pragma unroll 8
        for (int j4 = 0; j4 < H / 4; j4++) {
            float4 s = shv[j4], w = swv[j4];
            logit = fmaf(s.x, w.x, logit);
            logit = fmaf(s.y, w.y, logit);
            logit = fmaf(s.z, w.z, logit);
            logit = fmaf(s.w, w.w, logit);
        }
        g_prob[warp] = sigmoid_exact(logit);
    }
}

// ---------------- 2a. partial ranks over j-chunks (desc prob, asc-index ties) ----------------
__global__ void k_rank1() {
    __shared__ float sp[RCHN];      // 4 KB
    int tid = threadIdx.x;
    int jc = blockIdx.x & (RCH - 1);
    int ib = blockIdx.x >> 3;
    int jbase = jc * RCHN;
    for (int t = tid; t < RCHN; t += blockDim.x) sp[t] = g_prob[jbase + t];
    __syncthreads();
    int i = ib * 256 + tid;
    if (i >= N_IN) return;
    float pi = g_prob[i];
    int r = 0;
#pragma unroll 8
    for (int j = 0; j < RCHN; j++) {
        float pj = sp[j];
        r += (pj > pi) || (pj == pi && (jbase + j) < i);
    }
    atomicAdd(&g_rank[i], r);
}
// ---------------- 2b. scatter: sel[rank] = i ----------------
__global__ void k_rank2() {
    int i = blockIdx.x * blockDim.x + threadIdx.x;
    if (i >= N_IN) return;
    int r = g_rank[i];
    if (r < NS) g_sel[r] = i;
}

// ---------------- 3. gather sx/sp (vectorized), pack (x,y,z,|p|^2), grid-cell insert ----------------
__global__ void k_gather(const float* __restrict__ x, const float* __restrict__ pos) {
    int t = blockIdx.x * blockDim.x + threadIdx.x;
    if (t < NS * (D / 4)) {                      // float4 copy of sx
        int r = t >> 4, d4 = t & 15;
        ((float4*)g_sx)[t] = ((const float4*)x)[g_sel[r] * (D / 4) + d4];
    }
    if (t < NS * 3) {
        int r = t / 3, c = t % 3;
        g_sp[t] = pos[g_sel[r] * 3 + c];
    }
    if (t < NS) {
        int sI = g_sel[t];
        float a = pos[sI * 3], b = pos[sI * 3 + 1], c = pos[sI * 3 + 2];
        float sq = __fadd_rn(__fadd_rn(__fmul_rn(a, a), __fmul_rn(b, b)), __fmul_rn(c, c));
        g_sp4[t] = make_float4(a, b, c, sq);
        int ix = min(GRID - 1, max(0, (int)(a * GRID)));
        int iy = min(GRID - 1, max(0, (int)(b * GRID)));
        int iz = min(GRID - 1, max(0, (int)(c * GRID)));
        int cell = ix + GRID * (iy + GRID * iz);
        g_pcell[t] = cell;
        g_pslot[t] = atomicAdd(&g_ccnt[cell], 1);
    }
}

// ---------------- 3b. warp-shfl exclusive scan over 4096 cells + point scatter ----------------
__global__ void k_cscan() {
    __shared__ int warpsum[32];
    int tid = threadIdx.x;          // 1024
    int lane = tid & 31, wid = tid >> 5;
    int base = tid * 4;
    int v0 = g_ccnt[base], v1 = g_ccnt[base + 1], v2 = g_ccnt[base + 2], v3 = g_ccnt[base + 3];
    int s = v0 + v1 + v2 + v3;
    int sc = s;
#pragma unroll
    for (int o = 1; o < 32; o <<= 1) {
        int n = __shfl_up_sync(0xffffffffu, sc, o);
        if (lane >= o) sc += n;
    }
    if (lane == 31) warpsum[wid] = sc;
    __syncthreads();
    if (wid == 0) {
        int ws = warpsum[lane];
        int wsc = ws;
#pragma unroll
        for (int o = 1; o < 32; o <<= 1) {
            int n = __shfl_up_sync(0xffffffffu, wsc, o);
            if (lane >= o) wsc += n;
        }
        warpsum[lane] = wsc;
    }
    __syncthreads();
    int off = (wid > 0 ? warpsum[wid - 1] : 0) + (sc - s);
    g_cstart[base] = off;
    g_cstart[base + 1] = off + v0;
    g_cstart[base + 2] = off + v0 + v1;
    g_cstart[base + 3] = off + v0 + v1 + v2;
    __syncthreads();
    for (int t = tid; t < NS; t += 1024)
        g_cpts[g_cstart[g_pcell[t]] + g_pslot[t]] = t;
}

// ---------------- 4. grid-accelerated exact 15-NN, warp per i ----------------
__global__ void k_knn_space() {
    int i = (blockIdx.x * blockDim.x + threadIdx.x) >> 5;
    int lane = threadIdx.x & 31;
    if (i >= NS) return;
    float4 pi = g_sp4[i];
    int cx = min(GRID - 1, max(0, (int)(pi.x * GRID)));
    int cy = min(GRID - 1, max(0, (int)(pi.y * GRID)));
    int cz = min(GRID - 1, max(0, (int)(pi.z * GRID)));
    unsigned long long buf[EK];
#pragma unroll
    for (int t = 0; t < EK; t++) buf[t] = ~0ull;
    for (int r = 0; r < GRID; r++) {
        int s = 2 * r + 1;
        int ncub = s * s * s;
        for (int idx = lane; idx < ncub; idx += 32) {
            int dz = idx / (s * s) - r;
            int rem = idx % (s * s);
            int dy = rem / s - r;
            int dx = rem % s - r;
            int ch = abs(dx); if (abs(dy) > ch) ch = abs(dy); if (abs(dz) > ch) ch = abs(dz);
            if (ch != r) continue;   // shell only
            int ax = cx + dx, ay = cy + dy, az = cz + dz;
            if (ax < 0 || ax >= GRID || ay < 0 || ay >= GRID || az < 0 || az >= GRID) continue;
            int cell = ax + GRID * (ay + GRID * az);
            int st = g_cstart[cell];
            int cn = g_ccnt[cell];
            for (int p = 0; p < cn; p++) {
                int j = g_cpts[st + p];
                if (j == i) continue;
                float4 pj = g_sp4[j];
                float dot = fmaf(pi.z, pj.z, fmaf(pi.y, pj.y, __fmul_rn(pi.x, pj.x)));
                float d2 = __fsub_rn(__fadd_rn(pi.w, pj.w), __fmul_rn(2.0f, dot));
                unsigned long long key =
                    ((unsigned long long)f32_sortable(d2) << 32) | (unsigned int)j;
                if (key < buf[EK - 1]) {
                    buf[EK - 1] = key;
#pragma unroll
                    for (int t2 = EK - 1; t2 > 0; t2--) {
                        if (buf[t2] < buf[t2 - 1]) {
                            unsigned long long tmp = buf[t2]; buf[t2] = buf[t2 - 1]; buf[t2 - 1] = tmp;
                        }
                    }
                }
            }
        }
        __syncwarp();
        if (r >= 2) {
            float bound = (float)(r * r) * (1.0f / (GRID * GRID)) - 1e-5f;
            unsigned long long B = ((unsigned long long)f32_sortable(bound) << 32);
            int c = 0;
#pragma unroll
            for (int t = 0; t < EK; t++) c += (buf[t] < B);
#pragma unroll
            for (int o = 16; o > 0; o >>= 1) c += __shfl_xor_sync(0xffffffffu, c, o);
            if (c >= EK) break;
        }
    }
#pragma unroll 1
    for (int r = 0; r < EK; r++) {
        unsigned long long key = buf[0];
        unsigned long long kk = key;
#pragma unroll
        for (int o = 16; o > 0; o >>= 1) {
            unsigned long long o2 = __shfl_xor_sync(0xffffffffu, kk, o);
            if (o2 < kk) kk = o2;
        }
        if (lane == 0) g_nbr[i * EK + r] = (int)(kk & 0xFFFFFFFFull);
        if (key == kk) {
#pragma unroll
            for (int q = 0; q < EK - 1; q++) buf[q] = buf[q + 1];
            buf[EK - 1] = ~0ull;
        }
    }
}

// ---------------- 5. edge probs -> scatter into per-row buckets ----------------
// float4 loads, scalar ascending-d fma chain (bitwise identical, bitwise symmetric)
__global__ void k_edges(const float* __restrict__ w_e) {
    __shared__ float swe[D];
    if (threadIdx.x < D) swe[threadIdx.x] = w_e[threadIdx.x];
    __syncthreads();
    int e = blockIdx.x * blockDim.x + threadIdx.x;
    if (e >= NS * EK) return;
    int i = e / EK;
    int j = g_nbr[e];
    const float4* a4 = (const float4*)(g_sx + i * D);
    const float4* b4 = (const float4*)(g_sx + j * D);
    const float4* w4 = (const float4*)swe;
    float acc = 0.0f;
#pragma unroll 4
    for (int d4 = 0; d4 < D / 4; d4++) {
        float4 av = a4[d4], bv = b4[d4], wv = w4[d4];
        acc = fmaf(__fmul_rn(av.x, bv.x), wv.x, acc);
        acc = fmaf(__fmul_rn(av.y, bv.y), wv.y, acc);
        acc = fmaf(__fmul_rn(av.z, bv.z), wv.z, acc);
        acc = fmaf(__fmul_rn(av.w, bv.w), wv.w, acc);
    }
    float ep = sigmoid_exact(acc);
    int p1 = atomicAdd(&g_cnt[i], 1);
    if (p1 < MAXD) { g_scol[i * MAXD + p1] = j; g_sval[i * MAXD + p1] = ep; }
    int p2 = atomicAdd(&g_cnt[j], 1);
    if (p2 < MAXD) { g_scol[j * MAXD + p2] = i; g_sval[j * MAXD + p2] = ep; }
}

// ---------------- 6. per-row: sort by j, dedup, norm, deg (warp/row) ----------------
__global__ void k_rowsort() {
    __shared__ int   sj[4][MAXD];
    __shared__ float sv[4][MAXD];
    int gw   = (blockIdx.x * blockDim.x + threadIdx.x) >> 5;
    int wloc = (threadIdx.x >> 5);
    int lane = threadIdx.x & 31;
    if (gw >= NS) return;
    int n = min(g_cnt[gw], MAXD);
    int*   mj = sj[wloc];
    float* mv = sv[wloc];
    for (int t = lane; t < n; t += 32) { mj[t] = g_scol[gw * MAXD + t]; mv[t] = g_sval[gw * MAXD + t]; }
    __syncwarp();
    int   jr[8]; float vr[8]; int rr[8]; int ne = 0;
    for (int t = lane; t < n; t += 32) {
        int jt = mj[t]; float vt = mv[t];
        int r = 0;
        for (int m = 0; m < n; m++) {
            int jm = mj[m];
            r += (jm < jt) || (jm == jt && m < t);
        }
        jr[ne] = jt; vr[ne] = vt; rr[ne] = r; ne++;
    }
    __syncwarp();
    for (int q = 0; q < ne; q++) { mj[rr[q]] = jr[q]; mv[rr[q]] = vr[q]; }
    __syncwarp();
    if (lane == 0) {
        int cnt = 0, prev = -1;
        float s = 0.0f;
        for (int t = 0; t < n; t++) {
            int jt = mj[t];
            if (jt != prev) {
                float vt = mv[t];
                g_scol[gw * MAXD + cnt] = jt;
                g_sval[gw * MAXD + cnt] = vt;
                s = __fadd_rn(s, __fmul_rn(vt, vt));   // ascending-j chain
                cnt++; prev = jt;
            }
        }
        g_deg[gw] = cnt;
        g_norm[gw] = s;
    }
}

// ---------------- 7. fd2 top-16 via deterministic scatter SpGEMM (1 block/row, 256 thr) ----------------
// ascending-k sequential steps -> bitwise identical to reference dense fma chain
__global__ void k_fd2() {
    __shared__ float sdot[NS];          // 16 KB
    __shared__ int   scol[MAXD];
    __shared__ float sval[MAXD];
    __shared__ int   sdeg[MAXD];
    __shared__ unsigned long long swin[8];
    int i = blockIdx.x, tid = threadIdx.x;       // 256 threads
    int dg = g_deg[i];
    for (int t = tid; t < NS; t += 256) sdot[t] = 0.0f;
    if (tid < dg) { scol[tid] = g_scol[i * MAXD + tid]; sval[tid] = g_sval[i * MAXD + tid]; }
    __syncthreads();
    if (tid < dg) sdeg[tid] = g_deg[scol[tid]];   // prefetch all row degrees upfront
    __syncthreads();
    int jn = 0; float vn = 0.f; int dk_cur = 0;
    if (dg > 0) {
        int k = scol[0];
        dk_cur = sdeg[0];
        if (tid < dk_cur) { jn = g_scol[k * MAXD + tid]; vn = g_sval[k * MAXD + tid]; }
    }
    for (int u = 0; u < dg; u++) {
        float aik = sval[u];
        int j2 = 0; float v2 = 0.f; int dk_next = 0;
        if (u + 1 < dg) {
            int k2 = scol[u + 1];
            dk_next = sdeg[u + 1];
            if (tid < dk_next) { j2 = g_scol[k2 * MAXD + tid]; v2 = g_sval[k2 * MAXD + tid]; }
        }
        if (tid < dk_cur) sdot[jn] = fmaf(aik, vn, sdot[jn]);   // distinct j: race-free
        __syncthreads();
        dk_cur = dk_next; jn = j2; vn = v2;
    }
    float ni = g_norm[i];
    float bd[KNN]; int bj[KNN];
#pragma unroll
    for (int t = 0; t < KNN; t++) { bd[t] = INFINITY; bj[t] = 0x7FFFFFFF; }
    for (int j = tid; j < NS; j += 256) {
        if (j == i) continue;
        float fd2 = __fsub_rn(__fadd_rn(ni, g_norm[j]), __fmul_rn(2.0f, sdot[j]));
        if (fd2 < bd[KNN - 1]) {
            bd[KNN - 1] = fd2; bj[KNN - 1] = j;
#pragma unroll
            for (int t2 = KNN - 1; t2 > 0; t2--) {
                if (bd[t2] < bd[t2 - 1]) {
                    float a = bd[t2]; bd[t2] = bd[t2 - 1]; bd[t2 - 1] = a;
                    int   b = bj[t2]; bj[t2] = bj[t2 - 1]; bj[t2 - 1] = b;
                }
            }
        }
    }
    __syncthreads();
    int wid = tid >> 5, lane = tid & 31;
#pragma unroll 1
    for (int r = 0; r < KNN; r++) {
        unsigned long long key =
            ((unsigned long long)f32_sortable(bd[0]) << 32) | (unsigned int)bj[0];
        unsigned long long kk = key;
#pragma unroll
        for (int o = 16; o > 0; o >>= 1) {
            unsigned long long o2 = __shfl_xor_sync(0xffffffffu, kk, o);
            if (o2 < kk) kk = o2;
        }
        if (lane == 0) swin[wid] = kk;
        __syncthreads();
        unsigned long long w = swin[0];
#pragma unroll
        for (int q = 1; q < 8; q++) if (swin[q] < w) w = swin[q];
        if (tid == 0) g_knn[i * KNN + r] = (int)(w & 0xFFFFFFFFull);
        if (key == w) {
#pragma unroll
            for (int q = 0; q < KNN - 1; q++) { bd[q] = bd[q + 1]; bj[q] = bj[q + 1]; }
            bd[KNN - 1] = INFINITY; bj[KNN - 1] = 0x7FFFFFFF;
        }
        __syncthreads();
    }
}

// ---------------- 8. per-vertex MLP projection p_v = [sx_v, sp_v] @ Wf1 ----------------
__global__ void k_pfeat(const float* __restrict__ Wf1) {
    __shared__ float sW[(D + 3) * H];
    int tid = threadIdx.x;
    for (int t = tid; t < (D + 3) * H; t += blockDim.x) sW[t] = Wf1[t];
    __syncthreads();
    int warp = (blockIdx.x * blockDim.x + tid) >> 5;
    int lane = tid & 31;
    if (warp >= NS) return;
    const float4* xr = (const float4*)(g_sx + warp * D);
    float acc[4] = {0.f, 0.f, 0.f, 0.f};
#pragma unroll 4
    for (int d4 = 0; d4 < D / 4; d4++) {
        float4 xv = xr[d4];
        int d = d4 * 4;
#pragma unroll
        for (int q = 0; q < 4; q++) acc[q] = fmaf(xv.x, sW[(d + 0) * H + lane + q * 32], acc[q]);
#pragma unroll
        for (int q = 0; q < 4; q++) acc[q] = fmaf(xv.y, sW[(d + 1) * H + lane + q * 32], acc[q]);
#pragma unroll
        for (int q = 0; q < 4; q++) acc[q] = fmaf(xv.z, sW[(d + 2) * H + lane + q * 32], acc[q]);
#pragma unroll
        for (int q = 0; q < 4; q++) acc[q] = fmaf(xv.w, sW[(d + 3) * H + lane + q * 32], acc[q]);
    }
#pragma unroll
    for (int c = 0; c < 3; c++) {
        float pv = g_sp[warp * 3 + c];
#pragma unroll
        for (int q = 0; q < 4; q++) acc[q] = fmaf(pv, sW[(D + c) * H + lane + q * 32], acc[q]);
    }
#pragma unroll
    for (int q = 0; q < 4; q++) g_p[warp * H + lane + q * 32] = acc[q];
}

// ---------------- 9. triangles: fprob/tprob (1 block/row, thread/pair) ----------------
__global__ void k_tri(const float* __restrict__ bf1, const float* __restrict__ wf2,
                      float* __restrict__ out) {
    __shared__ float spn[KNN * 132];   // 132 % 4 == 0: float4-aligned rows
    __shared__ float spi[H];
    __shared__ float sb[H];
    __shared__ float sw[H];
    __shared__ int   sknn[KNN];
    __shared__ float sain[KNN];
    int i = blockIdx.x, tid = threadIdx.x;
    if (tid < KNN) sknn[tid] = g_knn[i * KNN + tid];
    if (tid < H) { spi[tid] = g_p[i * H + tid]; sb[tid] = bf1[tid]; sw[tid] = wf2[tid]; }
    __syncthreads();
    for (int t = tid; t < KNN * H; t += 128) {
        int r = t >> 7, h = t & 127;
        spn[r * 132 + h] = g_p[sknn[r] * H + h];
    }
    if (tid < KNN) sain[tid] = adj_lookup(i, sknn[tid]);
    __syncthreads();
    if (tid < NPAIR) {
        int rem = tid, jj = 0;
        while (rem >= EK - jj) { rem -= EK - jj; jj++; }
        int ll = jj + 1 + rem;
        int n1 = sknn[jj], n2 = sknn[ll];
        float a12 = adj_lookup(n1, n2);
        const float4* p1v = (const float4*)(spn + jj * 132);
        const float4* p2v = (const float4*)(spn + ll * 132);
        const float4* piv = (const float4*)spi;
        const float4* sbv = (const float4*)sb;
        const float4* swv = (const float4*)sw;
        float acc = 0.0f;
        const float third = 0.3333333333333333f;
#pragma unroll 8
        for (int h4 = 0; h4 < H / 4; h4++) {
            float4 a = piv[h4], b = p1v[h4], c = p2v[h4], bb = sbv[h4], ww = swv[h4];
            float pre;
            pre = fmaf(__fadd_rn(__fadd_rn(a.x, b.x), c.x), third, bb.x);
            acc = fmaf(fmaxf(pre, 0.0f), ww.x, acc);
            pre = fmaf(__fadd_rn(__fadd_rn(a.y, b.y), c.y), third, bb.y);
            acc = fmaf(fmaxf(pre, 0.0f), ww.y, acc);
            pre = fmaf(__fadd_rn(__fadd_rn(a.z, b.z), c.z), third, bb.z);
            acc = fmaf(fmaxf(pre, 0.0f), ww.z, acc);
            pre = fmaf(__fadd_rn(__fadd_rn(a.w, b.w), c.w), third, bb.w);
            acc = fmaf(fmaxf(pre, 0.0f), ww.w, acc);
        }
        float valid = (a12 > 0.0f) ? 1.0f : 0.0f;
        float fp = sigmoid_fast(acc) * valid;
        float prod = __fmul_rn(__fmul_rn(sain[jj], sain[ll]), a12);
        float tp = (a12 > 0.0f) ? cbrtf(fmaxf(prod, 1e-9f)) : 0.0f;
        out[(size_t)i * NPAIR + tid]                      = fp;
        out[(size_t)NS * NPAIR + (size_t)i * NPAIR + tid] = tp;
    }
}

// ---------------- launch ----------------
extern "C" void kernel_launch(void* const* d_in, const int* in_sizes, int n_in,
                              void* d_out, int out_size) {
    const float* x   = (const float*)d_in[0];
    const float* pos = (const float*)d_in[1];
    const float* W1  = (const float*)d_in[2];
    const float* b1  = (const float*)d_in[3];
    const float* w2  = (const float*)d_in[4];
    const float* w_e = (const float*)d_in[5];
    const float* Wf1 = (const float*)d_in[6];
    const float* bf1 = (const float*)d_in[7];
    const float* wf2 = (const float*)d_in[8];
    float* out = (float*)d_out;

    k_logits<<<(N_IN * 32 + 255) / 256, 256>>>(x, W1, b1, w2);
    k_rank1<<<((N_IN + 255) / 256) * RCH, 256>>>();
    k_rank2<<<(N_IN + 255) / 256, 256>>>();
    k_gather<<<(NS * D + 255) / 256, 256>>>(x, pos);
    k_cscan<<<1, 1024>>>();
    k_knn_space<<<(NS * 32 + 255) / 256, 256>>>();
    k_edges<<<(NS * EK + 255) / 256, 256>>>(w_e);
    k_rowsort<<<(NS * 32 + 127) / 128, 128>>>();
    k_fd2<<<NS, 256>>>();
    k_pfeat<<<(NS * 32 + 255) / 256, 256>>>(Wf1);
    k_tri<<<NS, 128>>>(bf1, wf2, out);
}

// round 13
// speedup vs baseline: 1.1741x; 1.1741x over previous
#include <cuda_runtime.h>
#include <math.h>

#define N_IN  8000
#define NS    4000
#define D     64
#define H     128
#define EK    15
#define KNN   16
#define NPAIR 120
#define MAXD  256
#define GRID  16
#define NCELL (GRID * GRID * GRID)
#define RCH   8
#define RCHN  (N_IN / RCH)   // 1000

// ---------------- scratch (no allocations allowed) ----------------
__device__ float g_prob[N_IN];
__device__ int   g_rank[N_IN];
__device__ int   g_sel[NS];
__device__ int   g_cnt[NS];
__device__ float g_sx[NS * D];
__device__ float g_sp[NS * 3];
__device__ float4 g_sp4[NS];
__device__ int   g_nbr[NS * EK];
__device__ int   g_deg[NS];
__device__ int   g_scol[NS * MAXD];    // unsorted buckets, then sorted CSR (in place)
__device__ float g_sval[NS * MAXD];
__device__ float g_norm[NS];
__device__ int   g_knn[NS * KNN];
__device__ float g_p[NS * H];
// spatial grid
__device__ int   g_ccnt[NCELL];
__device__ int   g_cstart[NCELL];
__device__ int   g_pcell[NS];
__device__ int   g_pslot[NS];
__device__ int   g_cpts[NS];

__device__ __forceinline__ float sigmoid_fast(float v) { return 1.0f / (1.0f + expf(-v)); }
// near-correctly-rounded fp32 sigmoid — matches libm expf bits
__device__ __forceinline__ float sigmoid_exact(float v) {
    float e = (float)exp(-(double)v);
    return __fdiv_rn(1.0f, __fadd_rn(1.0f, e));
}
__device__ __forceinline__ unsigned int f32_sortable(float f) {
    unsigned int b = __float_as_uint(f);
    return (b & 0x80000000u) ? ~b : (b | 0x80000000u);
}
// sorted-CSR point lookup (rows ascending in j)
__device__ __forceinline__ float adj_lookup(int r, int j) {
    const int* c = g_scol + r * MAXD;
    int n = g_deg[r];
    int lo = 0, hi = n;
    while (lo < hi) { int mid = (lo + hi) >> 1; if (c[mid] < j) lo = mid + 1; else hi = mid; }
    return (lo < n && c[lo] == j) ? g_sval[r * MAXD + lo] : 0.0f;
}

// ---------------- 1. probs = sigmoid(relu(x@W1 + b1) @ w2), Eigen bit-model ----------------
// Prologue also zeroes the counters consumed by later kernels (stream-ordered).
__global__ void k_logits(const float* __restrict__ x, const float* __restrict__ W1,
                         const float* __restrict__ b1, const float* __restrict__ w2) {
    __shared__ float sW[D * H];
    __shared__ float sw2[H];
    __shared__ float sb1[H];
    __shared__ float sh[8][H];
    int tid = threadIdx.x;
    int gt = blockIdx.x * blockDim.x + tid;
    if (gt < N_IN) g_rank[gt] = 0;
    if (gt < NS)   g_cnt[gt] = 0;
    if (gt < NCELL) g_ccnt[gt] = 0;
    for (int t = tid; t < D * H; t += blockDim.x) sW[t] = W1[t];
    if (tid < H) { sw2[tid] = w2[tid]; sb1[tid] = b1[tid]; }
    __syncthreads();
    int warp = gt >> 5;
    int wloc = (tid >> 5);
    int lane = tid & 31;
    if (warp >= N_IN) return;
    const float* xr = x + warp * D;
    float acc[4] = {0.f, 0.f, 0.f, 0.f};
#pragma unroll 8
    for (int d = 0; d < D; d++) {
        float xv = xr[d];
#pragma unroll
        for (int q = 0; q < 4; q++) acc[q] = fmaf(xv, sW[d * H + lane + q * 32], acc[q]);
    }
#pragma unroll
    for (int q = 0; q < 4; q++) {
        int j = lane + q * 32;
        sh[wloc][j] = fmaxf(__fadd_rn(acc[q], sb1[j]), 0.0f);
    }
    __syncwarp();
    if (lane == 0) {
        float logit = 0.0f;
#pragma unroll 8
        for (int j = 0; j < H; j++) logit = fmaf(sh[wloc][j], sw2[j], logit);
        g_prob[warp] = sigmoid_exact(logit);
    }
}

// ---------------- 2a. partial ranks over j-chunks (desc prob, asc-index ties) ----------------
__global__ void k_rank1() {
    __shared__ float sp[RCHN];      // 4 KB
    int tid = threadIdx.x;
    int jc = blockIdx.x & (RCH - 1);
    int ib = blockIdx.x >> 3;
    int jbase = jc * RCHN;
    for (int t = tid; t < RCHN; t += blockDim.x) sp[t] = g_prob[jbase + t];
    __syncthreads();
    int i = ib * 256 + tid;
    if (i >= N_IN) return;
    float pi = g_prob[i];
    int r = 0;
#pragma unroll 8
    for (int j = 0; j < RCHN; j++) {
        float pj = sp[j];
        r += (pj > pi) || (pj == pi && (jbase + j) < i);
    }
    atomicAdd(&g_rank[i], r);
}
// ---------------- 2b. scatter: sel[rank] = i ----------------
__global__ void k_rank2() {
    int i = blockIdx.x * blockDim.x + threadIdx.x;
    if (i >= N_IN) return;
    int r = g_rank[i];
    if (r < NS) g_sel[r] = i;
}

// ---------------- 3. gather sx/sp, pack (x,y,z,|p|^2), grid-cell insert ----------------
__global__ void k_gather(const float* __restrict__ x, const float* __restrict__ pos) {
    int t = blockIdx.x * blockDim.x + threadIdx.x;
    if (t < NS * D) {
        int r = t >> 6, d = t & 63;
        g_sx[t] = x[g_sel[r] * D + d];
    }
    if (t < NS * 3) {
        int r = t / 3, c = t % 3;
        g_sp[t] = pos[g_sel[r] * 3 + c];
    }
    if (t < NS) {
        int sI = g_sel[t];
        float a = pos[sI * 3], b = pos[sI * 3 + 1], c = pos[sI * 3 + 2];
        float sq = __fadd_rn(__fadd_rn(__fmul_rn(a, a), __fmul_rn(b, b)), __fmul_rn(c, c));
        g_sp4[t] = make_float4(a, b, c, sq);
        int ix = min(GRID - 1, max(0, (int)(a * GRID)));
        int iy = min(GRID - 1, max(0, (int)(b * GRID)));
        int iz = min(GRID - 1, max(0, (int)(c * GRID)));
        int cell = ix + GRID * (iy + GRID * iz);
        g_pcell[t] = cell;
        g_pslot[t] = atomicAdd(&g_ccnt[cell], 1);
    }
}

// ---------------- 3b. warp-shfl exclusive scan over 4096 cells + point scatter ----------------
__global__ void k_cscan() {
    __shared__ int warpsum[32];
    int tid = threadIdx.x;          // 1024
    int lane = tid & 31, wid = tid >> 5;
    int base = tid * 4;
    int v0 = g_ccnt[base], v1 = g_ccnt[base + 1], v2 = g_ccnt[base + 2], v3 = g_ccnt[base + 3];
    int s = v0 + v1 + v2 + v3;
    int sc = s;
#pragma unroll
    for (int o = 1; o < 32; o <<= 1) {
        int n = __shfl_up_sync(0xffffffffu, sc, o);
        if (lane >= o) sc += n;
    }
    if (lane == 31) warpsum[wid] = sc;
    __syncthreads();
    if (wid == 0) {
        int ws = warpsum[lane];
        int wsc = ws;
#pragma unroll
        for (int o = 1; o < 32; o <<= 1) {
            int n = __shfl_up_sync(0xffffffffu, wsc, o);
            if (lane >= o) wsc += n;
        }
        warpsum[lane] = wsc;
    }
    __syncthreads();
    int off = (wid > 0 ? warpsum[wid - 1] : 0) + (sc - s);
    g_cstart[base] = off;
    g_cstart[base + 1] = off + v0;
    g_cstart[base + 2] = off + v0 + v1;
    g_cstart[base + 3] = off + v0 + v1 + v2;
    __syncthreads();
    for (int t = tid; t < NS; t += 1024)
        g_cpts[g_cstart[g_pcell[t]] + g_pslot[t]] = t;
}

// ---------------- 4. grid-accelerated exact 15-NN, warp per i ----------------
__global__ void k_knn_space() {
    int i = (blockIdx.x * blockDim.x + threadIdx.x) >> 5;
    int lane = threadIdx.x & 31;
    if (i >= NS) return;
    float4 pi = g_sp4[i];
    int cx = min(GRID - 1, max(0, (int)(pi.x * GRID)));
    int cy = min(GRID - 1, max(0, (int)(pi.y * GRID)));
    int cz = min(GRID - 1, max(0, (int)(pi.z * GRID)));
    unsigned long long buf[EK];
#pragma unroll
    for (int t = 0; t < EK; t++) buf[t] = ~0ull;
    for (int r = 0; r < GRID; r++) {
        int s = 2 * r + 1;
        int ncub = s * s * s;
        for (int idx = lane; idx < ncub; idx += 32) {
            int dz = idx / (s * s) - r;
            int rem = idx % (s * s);
            int dy = rem / s - r;
            int dx = rem % s - r;
            int ch = abs(dx); if (abs(dy) > ch) ch = abs(dy); if (abs(dz) > ch) ch = abs(dz);
            if (ch != r) continue;   // shell only
            int ax = cx + dx, ay = cy + dy, az = cz + dz;
            if (ax < 0 || ax >= GRID || ay < 0 || ay >= GRID || az < 0 || az >= GRID) continue;
            int cell = ax + GRID * (ay + GRID * az);
            int st = g_cstart[cell];
            int cn = g_ccnt[cell];
            for (int p = 0; p < cn; p++) {
                int j = g_cpts[st + p];
                if (j == i) continue;
                float4 pj = g_sp4[j];
                float dot = fmaf(pi.z, pj.z, fmaf(pi.y, pj.y, __fmul_rn(pi.x, pj.x)));
                float d2 = __fsub_rn(__fadd_rn(pi.w, pj.w), __fmul_rn(2.0f, dot));
                unsigned long long key =
                    ((unsigned long long)f32_sortable(d2) << 32) | (unsigned int)j;
                if (key < buf[EK - 1]) {
                    buf[EK - 1] = key;
#pragma unroll
                    for (int t2 = EK - 1; t2 > 0; t2--) {
                        if (buf[t2] < buf[t2 - 1]) {
                            unsigned long long tmp = buf[t2]; buf[t2] = buf[t2 - 1]; buf[t2 - 1] = tmp;
                        }
                    }
                }
            }
        }
        __syncwarp();
        if (r >= 2) {
            float bound = (float)(r * r) * (1.0f / (GRID * GRID)) - 1e-5f;
            unsigned long long B = ((unsigned long long)f32_sortable(bound) << 32);
            int c = 0;
#pragma unroll
            for (int t = 0; t < EK; t++) c += (buf[t] < B);
#pragma unroll
            for (int o = 16; o > 0; o >>= 1) c += __shfl_xor_sync(0xffffffffu, c, o);
            if (c >= EK) break;
        }
    }
#pragma unroll 1
    for (int r = 0; r < EK; r++) {
        unsigned long long key = buf[0];
        unsigned long long kk = key;
#pragma unroll
        for (int o = 16; o > 0; o >>= 1) {
            unsigned long long o2 = __shfl_xor_sync(0xffffffffu, kk, o);
            if (o2 < kk) kk = o2;
        }
        if (lane == 0) g_nbr[i * EK + r] = (int)(kk & 0xFFFFFFFFull);
        if (key == kk) {
#pragma unroll
            for (int q = 0; q < EK - 1; q++) buf[q] = buf[q + 1];
            buf[EK - 1] = ~0ull;
        }
    }
}

// ---------------- 5. edge probs -> scatter into per-row buckets ----------------
// float4 loads; scalar ascending-d fma chain (bitwise identical, bitwise symmetric in (i,j))
__global__ void k_edges(const float* __restrict__ w_e) {
    __shared__ float swe[D];
    if (threadIdx.x < D) swe[threadIdx.x] = w_e[threadIdx.x];
    __syncthreads();
    int e = blockIdx.x * blockDim.x + threadIdx.x;
    if (e >= NS * EK) return;
    int i = e / EK;
    int j = g_nbr[e];
    const float4* a4 = (const float4*)(g_sx + i * D);
    const float4* b4 = (const float4*)(g_sx + j * D);
    const float4* w4 = (const float4*)swe;
    float acc = 0.0f;
#pragma unroll 4
    for (int d4 = 0; d4 < D / 4; d4++) {
        float4 av = a4[d4], bv = b4[d4], wv = w4[d4];
        acc = fmaf(__fmul_rn(av.x, bv.x), wv.x, acc);
        acc = fmaf(__fmul_rn(av.y, bv.y), wv.y, acc);
        acc = fmaf(__fmul_rn(av.z, bv.z), wv.z, acc);
        acc = fmaf(__fmul_rn(av.w, bv.w), wv.w, acc);
    }
    float ep = sigmoid_exact(acc);
    int p1 = atomicAdd(&g_cnt[i], 1);
    if (p1 < MAXD) { g_scol[i * MAXD + p1] = j; g_sval[i * MAXD + p1] = ep; }
    int p2 = atomicAdd(&g_cnt[j], 1);
    if (p2 < MAXD) { g_scol[j * MAXD + p2] = i; g_sval[j * MAXD + p2] = ep; }
}

// ---------------- 6. per-row: sort by j, dedup, norm, deg (warp/row) ----------------
__global__ void k_rowsort() {
    __shared__ int   sj[4][MAXD];
    __shared__ float sv[4][MAXD];
    int gw   = (blockIdx.x * blockDim.x + threadIdx.x) >> 5;
    int wloc = (threadIdx.x >> 5);
    int lane = threadIdx.x & 31;
    if (gw >= NS) return;
    int n = min(g_cnt[gw], MAXD);
    int*   mj = sj[wloc];
    float* mv = sv[wloc];
    for (int t = lane; t < n; t += 32) { mj[t] = g_scol[gw * MAXD + t]; mv[t] = g_sval[gw * MAXD + t]; }
    __syncwarp();
    int   jr[8]; float vr[8]; int rr[8]; int ne = 0;
    for (int t = lane; t < n; t += 32) {
        int jt = mj[t]; float vt = mv[t];
        int r = 0;
        for (int m = 0; m < n; m++) {
            int jm = mj[m];
            r += (jm < jt) || (jm == jt && m < t);
        }
        jr[ne] = jt; vr[ne] = vt; rr[ne] = r; ne++;
    }
    __syncwarp();
    for (int q = 0; q < ne; q++) { mj[rr[q]] = jr[q]; mv[rr[q]] = vr[q]; }
    __syncwarp();
    if (lane == 0) {
        int cnt = 0, prev = -1;
        float s = 0.0f;
        for (int t = 0; t < n; t++) {
            int jt = mj[t];
            if (jt != prev) {
                float vt = mv[t];
                g_scol[gw * MAXD + cnt] = jt;
                g_sval[gw * MAXD + cnt] = vt;
                s = __fadd_rn(s, __fmul_rn(vt, vt));   // ascending-j chain
                cnt++; prev = jt;
            }
        }
        g_deg[gw] = cnt;
        g_norm[gw] = s;
    }
}

// ---------------- 7. fd2 top-16 via deterministic scatter SpGEMM (1 block/row, 128 thr) ----------------
__global__ void k_fd2() {
    __shared__ float sdot[NS];          // 16 KB
    __shared__ int   scol[MAXD];
    __shared__ float sval[MAXD];
    __shared__ unsigned long long swin[4];
    int i = blockIdx.x, tid = threadIdx.x;       // 128 threads
    int dg = g_deg[i];
    for (int t = tid; t < NS; t += 128) sdot[t] = 0.0f;
    for (int t = tid; t < dg; t += 128) { scol[t] = g_scol[i * MAXD + t]; sval[t] = g_sval[i * MAXD + t]; }
    __syncthreads();
    int jn0 = 0, jn1 = 0; float vn0 = 0.f, vn1 = 0.f; int dk_cur = 0;
    if (dg > 0) {
        int k = scol[0];
        dk_cur = g_deg[k];
        const int* ck = g_scol + k * MAXD; const float* cv = g_sval + k * MAXD;
        if (tid < dk_cur)        { jn0 = ck[tid];        vn0 = cv[tid]; }
        if (tid + 128 < dk_cur)  { jn1 = ck[tid + 128];  vn1 = cv[tid + 128]; }
    }
    for (int u = 0; u < dg; u++) {
        float aik = sval[u];
        int j20 = 0, j21 = 0; float v20 = 0.f, v21 = 0.f; int dk_next = 0;
        if (u + 1 < dg) {
            int k2 = scol[u + 1];
            dk_next = g_deg[k2];
            const int* ck = g_scol + k2 * MAXD; const float* cv = g_sval + k2 * MAXD;
            if (tid < dk_next)       { j20 = ck[tid];       v20 = cv[tid]; }
            if (tid + 128 < dk_next) { j21 = ck[tid + 128]; v21 = cv[tid + 128]; }
        }
        if (tid < dk_cur)       sdot[jn0] = fmaf(aik, vn0, sdot[jn0]);
        if (tid + 128 < dk_cur) sdot[jn1] = fmaf(aik, vn1, sdot[jn1]);
        __syncthreads();
        dk_cur = dk_next; jn0 = j20; vn0 = v20; jn1 = j21; vn1 = v21;
    }
    float ni = g_norm[i];
    float bd[KNN]; int bj[KNN];
#pragma unroll
    for (int t = 0; t < KNN; t++) { bd[t] = INFINITY; bj[t] = 0x7FFFFFFF; }
    for (int j = tid; j < NS; j += 128) {
        if (j == i) continue;
        float fd2 = __fsub_rn(__fadd_rn(ni, g_norm[j]), __fmul_rn(2.0f, sdot[j]));
        if (fd2 < bd[KNN - 1]) {
            bd[KNN - 1] = fd2; bj[KNN - 1] = j;
#pragma unroll
            for (int t2 = KNN - 1; t2 > 0; t2--) {
                if (bd[t2] < bd[t2 - 1]) {
                    float a = bd[t2]; bd[t2] = bd[t2 - 1]; bd[t2 - 1] = a;
                    int   b = bj[t2]; bj[t2] = bj[t2 - 1]; bj[t2 - 1] = b;
                }
            }
        }
    }
    __syncthreads();
    int wid = tid >> 5, lane = tid & 31;
#pragma unroll 1
    for (int r = 0; r < KNN; r++) {
        unsigned long long key =
            ((unsigned long long)f32_sortable(bd[0]) << 32) | (unsigned int)bj[0];
        unsigned long long kk = key;
#pragma unroll
        for (int o = 16; o > 0; o >>= 1) {
            unsigned long long o2 = __shfl_xor_sync(0xffffffffu, kk, o);
            if (o2 < kk) kk = o2;
        }
        if (lane == 0) swin[wid] = kk;
        __syncthreads();
        unsigned long long w = swin[0];
#pragma unroll
        for (int q = 1; q < 4; q++) if (swin[q] < w) w = swin[q];
        if (tid == 0) g_knn[i * KNN + r] = (int)(w & 0xFFFFFFFFull);
        if (key == w) {
#pragma unroll
            for (int q = 0; q < KNN - 1; q++) { bd[q] = bd[q + 1]; bj[q] = bj[q + 1]; }
            bd[KNN - 1] = INFINITY; bj[KNN - 1] = 0x7FFFFFFF;
        }
        __syncthreads();
    }
}

// ---------------- 8. per-vertex MLP projection p_v = [sx_v, sp_v] @ Wf1 ----------------
__global__ void k_pfeat(const float* __restrict__ Wf1) {
    __shared__ float sW[(D + 3) * H];
    int tid = threadIdx.x;
    for (int t = tid; t < (D + 3) * H; t += blockDim.x) sW[t] = Wf1[t];
    __syncthreads();
    int warp = (blockIdx.x * blockDim.x + tid) >> 5;
    int lane = tid & 31;
    if (warp >= NS) return;
    float acc[4] = {0.f, 0.f, 0.f, 0.f};
#pragma unroll 8
    for (int d = 0; d < D; d++) {
        float xv = g_sx[warp * D + d];
#pragma unroll
        for (int q = 0; q < 4; q++) acc[q] = fmaf(xv, sW[d * H + lane + q * 32], acc[q]);
    }
#pragma unroll
    for (int c = 0; c < 3; c++) {
        float pv = g_sp[warp * 3 + c];
#pragma unroll
        for (int q = 0; q < 4; q++) acc[q] = fmaf(pv, sW[(D + c) * H + lane + q * 32], acc[q]);
    }
#pragma unroll
    for (int q = 0; q < 4; q++) g_p[warp * H + lane + q * 32] = acc[q];
}

// ---------------- 9. triangles: fprob/tprob (1 block/row, thread/pair) ----------------
__global__ void k_tri(const float* __restrict__ bf1, const float* __restrict__ wf2,
                      float* __restrict__ out) {
    __shared__ float spn[KNN * 132];
    __shared__ float spi[H];
    __shared__ float sb[H];
    __shared__ float sw[H];
    __shared__ int   sknn[KNN];
    __shared__ float sain[KNN];
    int i = blockIdx.x, tid = threadIdx.x;
    if (tid < KNN) sknn[tid] = g_knn[i * KNN + tid];
    if (tid < H) { spi[tid] = g_p[i * H + tid]; sb[tid] = bf1[tid]; sw[tid] = wf2[tid]; }
    __syncthreads();
    for (int t = tid; t < KNN * H; t += 128) {
        int r = t >> 7, h = t & 127;
        spn[r * 132 + h] = g_p[sknn[r] * H + h];
    }
    if (tid < KNN) sain[tid] = adj_lookup(i, sknn[tid]);
    __syncthreads();
    if (tid < NPAIR) {
        int rem = tid, jj = 0;
        while (rem >= EK - jj) { rem -= EK - jj; jj++; }
        int ll = jj + 1 + rem;
        int n1 = sknn[jj], n2 = sknn[ll];
        float a12 = adj_lookup(n1, n2);
        const float* p1 = spn + jj * 132;
        const float* p2 = spn + ll * 132;
        float acc = 0.0f;
        const float third = 0.3333333333333333f;
#pragma unroll 8
        for (int h = 0; h < H; h++) {
            // continuous-output path: (sum*1/3 + b) vs (sum/3 + b) differs ~1ulp, OK
            float pre = fmaf(__fadd_rn(__fadd_rn(spi[h], p1[h]), p2[h]), third, sb[h]);
            acc = fmaf(fmaxf(pre, 0.0f), sw[h], acc);
        }
        float valid = (a12 > 0.0f) ? 1.0f : 0.0f;
        float fp = sigmoid_fast(acc) * valid;
        float prod = __fmul_rn(__fmul_rn(sain[jj], sain[ll]), a12);
        float tp = (a12 > 0.0f) ? cbrtf(fmaxf(prod, 1e-9f)) : 0.0f;
        out[(size_t)i * NPAIR + tid]                      = fp;
        out[(size_t)NS * NPAIR + (size_t)i * NPAIR + tid] = tp;
    }
}

// ---------------- launch ----------------
extern "C" void kernel_launch(void* const* d_in, const int* in_sizes, int n_in,
                              void* d_out, int out_size) {
    const float* x   = (const float*)d_in[0];
    const float* pos = (const float*)d_in[1];
    const float* W1  = (const float*)d_in[2];
    const float* b1  = (const float*)d_in[3];
    const float* w2  = (const float*)d_in[4];
    const float* w_e = (const float*)d_in[5];
    const float* Wf1 = (const float*)d_in[6];
    const float* bf1 = (const float*)d_in[7];
    const float* wf2 = (const float*)d_in[8];
    float* out = (float*)d_out;

    k_logits<<<(N_IN * 32 + 255) / 256, 256>>>(x, W1, b1, w2);
    k_rank1<<<((N_IN + 255) / 256) * RCH, 256>>>();
    k_rank2<<<(N_IN + 255) / 256, 256>>>();
    k_gather<<<(NS * D + 255) / 256, 256>>>(x, pos);
    k_cscan<<<1, 1024>>>();
    k_knn_space<<<(NS * 32 + 255) / 256, 256>>>();
    k_edges<<<(NS * EK + 255) / 256, 256>>>(w_e);
    k_rowsort<<<(NS * 32 + 127) / 128, 128>>>();
    k_fd2<<<NS, 128>>>();
    k_pfeat<<<(NS * 32 + 255) / 256, 256>>>(Wf1);
    k_tri<<<NS, 128>>>(bf1, wf2, out);
}

// round 15
// speedup vs baseline: 1.1840x; 1.0084x over previous
#include <cuda_runtime.h>
#include <math.h>

#define N_IN  8000
#define NS    4000
#define D     64
#define H     128
#define EK    15
#define KNN   16
#define NPAIR 120
#define MAXD  256
#define GRID  16
#define NCELL (GRID * GRID * GRID)
#define RCH   8
#define RCHN  (N_IN / RCH)   // 1000

// ---------------- scratch (no allocations allowed) ----------------
__device__ float g_prob[N_IN];
__device__ int   g_rank[N_IN];
__device__ int   g_sel[NS];
__device__ int   g_cnt[NS];
__device__ float g_sx[NS * D];
__device__ float g_sp[NS * 3];
__device__ float4 g_sp4[NS];
__device__ int   g_nbr[NS * EK];
__device__ int   g_deg[NS];
__device__ int   g_scol[NS * MAXD];    // unsorted buckets, then sorted CSR (in place)
__device__ float g_sval[NS * MAXD];
__device__ float g_norm[NS];
__device__ int   g_knn[NS * KNN];
__device__ float g_p[NS * H];
// spatial grid
__device__ int   g_ccnt[NCELL];
__device__ int   g_cstart[NCELL];
__device__ int   g_pcell[NS];
__device__ int   g_pslot[NS];
__device__ int   g_cpts[NS];

__device__ __forceinline__ float sigmoid_fast(float v) { return 1.0f / (1.0f + expf(-v)); }
// near-correctly-rounded fp32 sigmoid — matches libm expf bits
__device__ __forceinline__ float sigmoid_exact(float v) {
    float e = (float)exp(-(double)v);
    return __fdiv_rn(1.0f, __fadd_rn(1.0f, e));
}
__device__ __forceinline__ unsigned int f32_sortable(float f) {
    unsigned int b = __float_as_uint(f);
    return (b & 0x80000000u) ? ~b : (b | 0x80000000u);
}
// sorted-CSR point lookup (rows ascending in j)
__device__ __forceinline__ float adj_lookup(int r, int j) {
    const int* c = g_scol + r * MAXD;
    int n = g_deg[r];
    int lo = 0, hi = n;
    while (lo < hi) { int mid = (lo + hi) >> 1; if (c[mid] < j) lo = mid + 1; else hi = mid; }
    return (lo < n && c[lo] == j) ? g_sval[r * MAXD + lo] : 0.0f;
}

// ---------------- 1. probs = sigmoid(relu(x@W1 + b1) @ w2), Eigen bit-model ----------------
// Prologue also zeroes the counters consumed by later kernels (stream-ordered).
__global__ void k_logits(const float* __restrict__ x, const float* __restrict__ W1,
                         const float* __restrict__ b1, const float* __restrict__ w2) {
    __shared__ float sW[D * H];
    __shared__ float sw2[H];
    __shared__ float sb1[H];
    __shared__ float sh[8][H];
    int tid = threadIdx.x;
    int gt = blockIdx.x * blockDim.x + tid;
    if (gt < N_IN) g_rank[gt] = 0;
    if (gt < NS)   g_cnt[gt] = 0;
    if (gt < NCELL) g_ccnt[gt] = 0;
    for (int t = tid; t < D * H; t += blockDim.x) sW[t] = W1[t];
    if (tid < H) { sw2[tid] = w2[tid]; sb1[tid] = b1[tid]; }
    __syncthreads();
    int warp = gt >> 5;
    int wloc = (tid >> 5);
    int lane = tid & 31;
    if (warp >= N_IN) return;
    const float* xr = x + warp * D;
    float acc[4] = {0.f, 0.f, 0.f, 0.f};
#pragma unroll 8
    for (int d = 0; d < D; d++) {
        float xv = xr[d];
#pragma unroll
        for (int q = 0; q < 4; q++) acc[q] = fmaf(xv, sW[d * H + lane + q * 32], acc[q]);
    }
#pragma unroll
    for (int q = 0; q < 4; q++) {
        int j = lane + q * 32;
        sh[wloc][j] = fmaxf(__fadd_rn(acc[q], sb1[j]), 0.0f);
    }
    __syncwarp();
    if (lane == 0) {
        float logit = 0.0f;
#pragma unroll 8
        for (int j = 0; j < H; j++) logit = fmaf(sh[wloc][j], sw2[j], logit);
        g_prob[warp] = sigmoid_exact(logit);
    }
}

// ---------------- 2a. partial ranks over j-chunks (desc prob, asc-index ties) ----------------
__global__ void k_rank1() {
    __shared__ float sp[RCHN];      // 4 KB
    int tid = threadIdx.x;
    int jc = blockIdx.x & (RCH - 1);
    int ib = blockIdx.x >> 3;
    int jbase = jc * RCHN;
    for (int t = tid; t < RCHN; t += blockDim.x) sp[t] = g_prob[jbase + t];
    __syncthreads();
    int i = ib * 256 + tid;
    if (i >= N_IN) return;
    float pi = g_prob[i];
    int r = 0;
#pragma unroll 8
    for (int j = 0; j < RCHN; j++) {
        float pj = sp[j];
        r += (pj > pi) || (pj == pi && (jbase + j) < i);
    }
    atomicAdd(&g_rank[i], r);
}
// ---------------- 2b. scatter: sel[rank] = i ----------------
__global__ void k_rank2() {
    int i = blockIdx.x * blockDim.x + threadIdx.x;
    if (i >= N_IN) return;
    int r = g_rank[i];
    if (r < NS) g_sel[r] = i;
}

// ---------------- 3. gather sx/sp, pack (x,y,z,|p|^2), grid-cell insert ----------------
__global__ void k_gather(const float* __restrict__ x, const float* __restrict__ pos) {
    int t = blockIdx.x * blockDim.x + threadIdx.x;
    if (t < NS * D) {
        int r = t >> 6, d = t & 63;
        g_sx[t] = x[g_sel[r] * D + d];
    }
    if (t < NS * 3) {
        int r = t / 3, c = t % 3;
        g_sp[t] = pos[g_sel[r] * 3 + c];
    }
    if (t < NS) {
        int sI = g_sel[t];
        float a = pos[sI * 3], b = pos[sI * 3 + 1], c = pos[sI * 3 + 2];
        float sq = __fadd_rn(__fadd_rn(__fmul_rn(a, a), __fmul_rn(b, b)), __fmul_rn(c, c));
        g_sp4[t] = make_float4(a, b, c, sq);
        int ix = min(GRID - 1, max(0, (int)(a * GRID)));
        int iy = min(GRID - 1, max(0, (int)(b * GRID)));
        int iz = min(GRID - 1, max(0, (int)(c * GRID)));
        int cell = ix + GRID * (iy + GRID * iz);
        g_pcell[t] = cell;
        g_pslot[t] = atomicAdd(&g_ccnt[cell], 1);
    }
}

// ---------------- 3b. warp-shfl exclusive scan over 4096 cells + point scatter ----------------
__global__ void k_cscan() {
    __shared__ int warpsum[32];
    int tid = threadIdx.x;          // 1024
    int lane = tid & 31, wid = tid >> 5;
    int base = tid * 4;
    int v0 = g_ccnt[base], v1 = g_ccnt[base + 1], v2 = g_ccnt[base + 2], v3 = g_ccnt[base + 3];
    int s = v0 + v1 + v2 + v3;
    int sc = s;
#pragma unroll
    for (int o = 1; o < 32; o <<= 1) {
        int n = __shfl_up_sync(0xffffffffu, sc, o);
        if (lane >= o) sc += n;
    }
    if (lane == 31) warpsum[wid] = sc;
    __syncthreads();
    if (wid == 0) {
        int ws = warpsum[lane];
        int wsc = ws;
#pragma unroll
        for (int o = 1; o < 32; o <<= 1) {
            int n = __shfl_up_sync(0xffffffffu, wsc, o);
            if (lane >= o) wsc += n;
        }
        warpsum[lane] = wsc;
    }
    __syncthreads();
    int off = (wid > 0 ? warpsum[wid - 1] : 0) + (sc - s);
    g_cstart[base] = off;
    g_cstart[base + 1] = off + v0;
    g_cstart[base + 2] = off + v0 + v1;
    g_cstart[base + 3] = off + v0 + v1 + v2;
    __syncthreads();
    for (int t = tid; t < NS; t += 1024)
        g_cpts[g_cstart[g_pcell[t]] + g_pslot[t]] = t;
}

// ---------------- 4. grid-accelerated exact 15-NN, warp per i ----------------
__global__ void k_knn_space() {
    int i = (blockIdx.x * blockDim.x + threadIdx.x) >> 5;
    int lane = threadIdx.x & 31;
    if (i >= NS) return;
    float4 pi = g_sp4[i];
    int cx = min(GRID - 1, max(0, (int)(pi.x * GRID)));
    int cy = min(GRID - 1, max(0, (int)(pi.y * GRID)));
    int cz = min(GRID - 1, max(0, (int)(pi.z * GRID)));
    unsigned long long buf[EK];
#pragma unroll
    for (int t = 0; t < EK; t++) buf[t] = ~0ull;
    for (int r = 0; r < GRID; r++) {
        int s = 2 * r + 1;
        int ncub = s * s * s;
        for (int idx = lane; idx < ncub; idx += 32) {
            int dz = idx / (s * s) - r;
            int rem = idx % (s * s);
            int dy = rem / s - r;
            int dx = rem % s - r;
            int ch = abs(dx); if (abs(dy) > ch) ch = abs(dy); if (abs(dz) > ch) ch = abs(dz);
            if (ch != r) continue;   // shell only
            int ax = cx + dx, ay = cy + dy, az = cz + dz;
            if (ax < 0 || ax >= GRID || ay < 0 || ay >= GRID || az < 0 || az >= GRID) continue;
            int cell = ax + GRID * (ay + GRID * az);
            int st = g_cstart[cell];
            int cn = g_ccnt[cell];
            for (int p = 0; p < cn; p++) {
                int j = g_cpts[st + p];
                if (j == i) continue;
                float4 pj = g_sp4[j];
                float dot = fmaf(pi.z, pj.z, fmaf(pi.y, pj.y, __fmul_rn(pi.x, pj.x)));
                float d2 = __fsub_rn(__fadd_rn(pi.w, pj.w), __fmul_rn(2.0f, dot));
                unsigned long long key =
                    ((unsigned long long)f32_sortable(d2) << 32) | (unsigned int)j;
                if (key < buf[EK - 1]) {
                    buf[EK - 1] = key;
#pragma unroll
                    for (int t2 = EK - 1; t2 > 0; t2--) {
                        if (buf[t2] < buf[t2 - 1]) {
                            unsigned long long tmp = buf[t2]; buf[t2] = buf[t2 - 1]; buf[t2 - 1] = tmp;
                        }
                    }
                }
            }
        }
        __syncwarp();
        if (r >= 2) {
            float bound = (float)(r * r) * (1.0f / (GRID * GRID)) - 1e-5f;
            unsigned long long B = ((unsigned long long)f32_sortable(bound) << 32);
            int c = 0;
#pragma unroll
            for (int t = 0; t < EK; t++) c += (buf[t] < B);
#pragma unroll
            for (int o = 16; o > 0; o >>= 1) c += __shfl_xor_sync(0xffffffffu, c, o);
            if (c >= EK) break;
        }
    }
#pragma unroll 1
    for (int r = 0; r < EK; r++) {
        unsigned long long key = buf[0];
        unsigned long long kk = key;
#pragma unroll
        for (int o = 16; o > 0; o >>= 1) {
            unsigned long long o2 = __shfl_xor_sync(0xffffffffu, kk, o);
            if (o2 < kk) kk = o2;
        }
        if (lane == 0) g_nbr[i * EK + r] = (int)(kk & 0xFFFFFFFFull);
        if (key == kk) {
#pragma unroll
            for (int q = 0; q < EK - 1; q++) buf[q] = buf[q + 1];
            buf[EK - 1] = ~0ull;
        }
    }
}

// ---------------- 5. edge probs -> scatter into per-row buckets ----------------
// float4 loads; scalar ascending-d fma chain (bitwise identical, bitwise symmetric in (i,j))
__global__ void k_edges(const float* __restrict__ w_e) {
    __shared__ float swe[D];
    if (threadIdx.x < D) swe[threadIdx.x] = w_e[threadIdx.x];
    __syncthreads();
    int e = blockIdx.x * blockDim.x + threadIdx.x;
    if (e >= NS * EK) return;
    int i = e / EK;
    int j = g_nbr[e];
    const float4* a4 = (const float4*)(g_sx + i * D);
    const float4* b4 = (const float4*)(g_sx + j * D);
    const float4* w4 = (const float4*)swe;
    float acc = 0.0f;
#pragma unroll 4
    for (int d4 = 0; d4 < D / 4; d4++) {
        float4 av = a4[d4], bv = b4[d4], wv = w4[d4];
        acc = fmaf(__fmul_rn(av.x, bv.x), wv.x, acc);
        acc = fmaf(__fmul_rn(av.y, bv.y), wv.y, acc);
        acc = fmaf(__fmul_rn(av.z, bv.z), wv.z, acc);
        acc = fmaf(__fmul_rn(av.w, bv.w), wv.w, acc);
    }
    float ep = sigmoid_exact(acc);
    int p1 = atomicAdd(&g_cnt[i], 1);
    if (p1 < MAXD) { g_scol[i * MAXD + p1] = j; g_sval[i * MAXD + p1] = ep; }
    int p2 = atomicAdd(&g_cnt[j], 1);
    if (p2 < MAXD) { g_scol[j * MAXD + p2] = i; g_sval[j * MAXD + p2] = ep; }
}

// ---------------- 6. per-row: sort by j, dedup, norm, deg (warp/row) ----------------
__global__ void k_rowsort() {
    __shared__ int   sj[4][MAXD];
    __shared__ float sv[4][MAXD];
    int gw   = (blockIdx.x * blockDim.x + threadIdx.x) >> 5;
    int wloc = (threadIdx.x >> 5);
    int lane = threadIdx.x & 31;
    if (gw >= NS) return;
    int n = min(g_cnt[gw], MAXD);
    int*   mj = sj[wloc];
    float* mv = sv[wloc];
    for (int t = lane; t < n; t += 32) { mj[t] = g_scol[gw * MAXD + t]; mv[t] = g_sval[gw * MAXD + t]; }
    __syncwarp();
    int   jr[8]; float vr[8]; int rr[8]; int ne = 0;
    for (int t = lane; t < n; t += 32) {
        int jt = mj[t]; float vt = mv[t];
        int r = 0;
        for (int m = 0; m < n; m++) {
            int jm = mj[m];
            r += (jm < jt) || (jm == jt && m < t);
        }
        jr[ne] = jt; vr[ne] = vt; rr[ne] = r; ne++;
    }
    __syncwarp();
    for (int q = 0; q < ne; q++) { mj[rr[q]] = jr[q]; mv[rr[q]] = vr[q]; }
    __syncwarp();
    if (lane == 0) {
        int cnt = 0, prev = -1;
        float s = 0.0f;
        for (int t = 0; t < n; t++) {
            int jt = mj[t];
            if (jt != prev) {
                float vt = mv[t];
                g_scol[gw * MAXD + cnt] = jt;
                g_sval[gw * MAXD + cnt] = vt;
                s = __fadd_rn(s, __fmul_rn(vt, vt));   // ascending-j chain
                cnt++; prev = jt;
            }
        }
        g_deg[gw] = cnt;
        g_norm[gw] = s;
    }
}

// ---------------- 7. fd2 top-16 via deterministic scatter SpGEMM (1 block/row, 128 thr) ----------------
// Single change vs round 13: all neighbor-row degrees prefetched into sdeg[] upfront,
// removing one level of the per-step dependent gmem chain. Scatter order unchanged.
__global__ void k_fd2() {
    __shared__ float sdot[NS];          // 16 KB
    __shared__ int   scol[MAXD];
    __shared__ float sval[MAXD];
    __shared__ short sdeg[MAXD];
    __shared__ unsigned long long swin[4];
    int i = blockIdx.x, tid = threadIdx.x;       // 128 threads
    int dg = g_deg[i];
    for (int t = tid; t < NS; t += 128) sdot[t] = 0.0f;
    for (int t = tid; t < dg; t += 128) { scol[t] = g_scol[i * MAXD + t]; sval[t] = g_sval[i * MAXD + t]; }
    __syncthreads();
    for (int t = tid; t < dg; t += 128) sdeg[t] = (short)g_deg[scol[t]];
    __syncthreads();
    int jn0 = 0, jn1 = 0; float vn0 = 0.f, vn1 = 0.f; int dk_cur = 0;
    if (dg > 0) {
        int k = scol[0];
        dk_cur = sdeg[0];
        const int* ck = g_scol + k * MAXD; const float* cv = g_sval + k * MAXD;
        if (tid < dk_cur)        { jn0 = ck[tid];        vn0 = cv[tid]; }
        if (tid + 128 < dk_cur)  { jn1 = ck[tid + 128];  vn1 = cv[tid + 128]; }
    }
    for (int u = 0; u < dg; u++) {
        float aik = sval[u];
        int j20 = 0, j21 = 0; float v20 = 0.f, v21 = 0.f; int dk_next = 0;
        if (u + 1 < dg) {
            int k2 = scol[u + 1];
            dk_next = sdeg[u + 1];
            const int* ck = g_scol + k2 * MAXD; const float* cv = g_sval + k2 * MAXD;
            if (tid < dk_next)       { j20 = ck[tid];       v20 = cv[tid]; }
            if (tid + 128 < dk_next) { j21 = ck[tid + 128]; v21 = cv[tid + 128]; }
        }
        if (tid < dk_cur)       sdot[jn0] = fmaf(aik, vn0, sdot[jn0]);
        if (tid + 128 < dk_cur) sdot[jn1] = fmaf(aik, vn1, sdot[jn1]);
        __syncthreads();
        dk_cur = dk_next; jn0 = j20; vn0 = v20; jn1 = j21; vn1 = v21;
    }
    float ni = g_norm[i];
    float bd[KNN]; int bj[KNN];
#pragma unroll
    for (int t = 0; t < KNN; t++) { bd[t] = INFINITY; bj[t] = 0x7FFFFFFF; }
    for (int j = tid; j < NS; j += 128) {
        if (j == i) continue;
        float fd2 = __fsub_rn(__fadd_rn(ni, g_norm[j]), __fmul_rn(2.0f, sdot[j]));
        if (fd2 < bd[KNN - 1]) {
            bd[KNN - 1] = fd2; bj[KNN - 1] = j;
#pragma unroll
            for (int t2 = KNN - 1; t2 > 0; t2--) {
                if (bd[t2] < bd[t2 - 1]) {
                    float a = bd[t2]; bd[t2] = bd[t2 - 1]; bd[t2 - 1] = a;
                    int   b = bj[t2]; bj[t2] = bj[t2 - 1]; bj[t2 - 1] = b;
                }
            }
        }
    }
    __syncthreads();
    int wid = tid >> 5, lane = tid & 31;
#pragma unroll 1
    for (int r = 0; r < KNN; r++) {
        unsigned long long key =
            ((unsigned long long)f32_sortable(bd[0]) << 32) | (unsigned int)bj[0];
        unsigned long long kk = key;
#pragma unroll
        for (int o = 16; o > 0; o >>= 1) {
            unsigned long long o2 = __shfl_xor_sync(0xffffffffu, kk, o);
            if (o2 < kk) kk = o2;
        }
        if (lane == 0) swin[wid] = kk;
        __syncthreads();
        unsigned long long w = swin[0];
#pragma unroll
        for (int q = 1; q < 4; q++) if (swin[q] < w) w = swin[q];
        if (tid == 0) g_knn[i * KNN + r] = (int)(w & 0xFFFFFFFFull);
        if (key == w) {
#pragma unroll
            for (int q = 0; q < KNN - 1; q++) { bd[q] = bd[q + 1]; bj[q] = bj[q + 1]; }
            bd[KNN - 1] = INFINITY; bj[KNN - 1] = 0x7FFFFFFF;
        }
        __syncthreads();
    }
}

// ---------------- 8. per-vertex MLP projection p_v = [sx_v, sp_v] @ Wf1 ----------------
__global__ void k_pfeat(const float* __restrict__ Wf1) {
    __shared__ float sW[(D + 3) * H];
    int tid = threadIdx.x;
    for (int t = tid; t < (D + 3) * H; t += blockDim.x) sW[t] = Wf1[t];
    __syncthreads();
    int warp = (blockIdx.x * blockDim.x + tid) >> 5;
    int lane = tid & 31;
    if (warp >= NS) return;
    float acc[4] = {0.f, 0.f, 0.f, 0.f};
#pragma unroll 8
    for (int d = 0; d < D; d++) {
        float xv = g_sx[warp * D + d];
#pragma unroll
        for (int q = 0; q < 4; q++) acc[q] = fmaf(xv, sW[d * H + lane + q * 32], acc[q]);
    }
#pragma unroll
    for (int c = 0; c < 3; c++) {
        float pv = g_sp[warp * 3 + c];
#pragma unroll
        for (int q = 0; q < 4; q++) acc[q] = fmaf(pv, sW[(D + c) * H + lane + q * 32], acc[q]);
    }
#pragma unroll
    for (int q = 0; q < 4; q++) g_p[warp * H + lane + q * 32] = acc[q];
}

// ---------------- 9. triangles: fprob/tprob (1 block/row, thread/pair) ----------------
__global__ void k_tri(const float* __restrict__ bf1, const float* __restrict__ wf2,
                      float* __restrict__ out) {
    __shared__ float spn[KNN * 132];
    __shared__ float spi[H];
    __shared__ float sb[H];
    __shared__ float sw[H];
    __shared__ int   sknn[KNN];
    __shared__ float sain[KNN];
    int i = blockIdx.x, tid = threadIdx.x;
    if (tid < KNN) sknn[tid] = g_knn[i * KNN + tid];
    if (tid < H) { spi[tid] = g_p[i * H + tid]; sb[tid] = bf1[tid]; sw[tid] = wf2[tid]; }
    __syncthreads();
    for (int t = tid; t < KNN * H; t += 128) {
        int r = t >> 7, h = t & 127;
        spn[r * 132 + h] = g_p[sknn[r] * H + h];
    }
    if (tid < KNN) sain[tid] = adj_lookup(i, sknn[tid]);
    __syncthreads();
    if (tid < NPAIR) {
        int rem = tid, jj = 0;
        while (rem >= EK - jj) { rem -= EK - jj; jj++; }
        int ll = jj + 1 + rem;
        int n1 = sknn[jj], n2 = sknn[ll];
        float a12 = adj_lookup(n1, n2);
        const float* p1 = spn + jj * 132;
        const float* p2 = spn + ll * 132;
        float acc = 0.0f;
        const float third = 0.3333333333333333f;
#pragma unroll 8
        for (int h = 0; h < H; h++) {
            // continuous-output path: (sum*1/3 + b) vs (sum/3 + b) differs ~1ulp, OK
            float pre = fmaf(__fadd_rn(__fadd_rn(spi[h], p1[h]), p2[h]), third, sb[h]);
            acc = fmaf(fmaxf(pre, 0.0f), sw[h], acc);
        }
        float valid = (a12 > 0.0f) ? 1.0f : 0.0f;
        float fp = sigmoid_fast(acc) * valid;
        float prod = __fmul_rn(__fmul_rn(sain[jj], sain[ll]), a12);
        float tp = (a12 > 0.0f) ? cbrtf(fmaxf(prod, 1e-9f)) : 0.0f;
        out[(size_t)i * NPAIR + tid]                      = fp;
        out[(size_t)NS * NPAIR + (size_t)i * NPAIR + tid] = tp;
    }
}

// ---------------- launch ----------------
extern "C" void kernel_launch(void* const* d_in, const int* in_sizes, int n_in,
                              void* d_out, int out_size) {
    const float* x   = (const float*)d_in[0];
    const float* pos = (const float*)d_in[1];
    const float* W1  = (const float*)d_in[2];
    const float* b1  = (const float*)d_in[3];
    const float* w2  = (const float*)d_in[4];
    const float* w_e = (const float*)d_in[5];
    const float* Wf1 = (const float*)d_in[6];
    const float* bf1 = (const float*)d_in[7];
    const float* wf2 = (const float*)d_in[8];
    float* out = (float*)d_out;

    k_logits<<<(N_IN * 32 + 255) / 256, 256>>>(x, W1, b1, w2);
    k_rank1<<<((N_IN + 255) / 256) * RCH, 256>>>();
    k_rank2<<<(N_IN + 255) / 256, 256>>>();
    k_gather<<<(NS * D + 255) / 256, 256>>>(x, pos);
    k_cscan<<<1, 1024>>>();
    k_knn_space<<<(NS * 32 + 255) / 256, 256>>>();
    k_edges<<<(NS * EK + 255) / 256, 256>>>(w_e);
    k_rowsort<<<(NS * 32 + 127) / 128, 128>>>();
    k_fd2<<<NS, 128>>>();
    k_pfeat<<<(NS * 32 + 255) / 256, 256>>>(Wf1);
    k_tri<<<NS, 128>>>(bf1, wf2, out);
}